// round 9
// baseline (speedup 1.0000x reference)
#include <cuda_runtime.h>
#include <cstdint>
#include <mma.h>
#include <math.h>

using namespace nvcuda;

#define BB 16      // batch
#define NR 512     // real points
#define NP 384     // padding points
#define NT 896     // total points per side
#define DD 256     // feature dim

// ---------------- scratch ----------------
__device__ float d_f1n[BB*NT*DD];       // normalized f1 (tf32-rounded)
__device__ float d_f2n[BB*NT*DD];       // normalized f2 (tf32-rounded)
__device__ float d_x3r[BB*NP*DD];       // tf32-rounded raw x3
__device__ float d_x4r[BB*NP*DD];       // tf32-rounded raw x4
__device__ float d_S  [BB*NR*NR];       // S then C (in-place)
__device__ float d_CT [BB*NR*NR];       // C transposed
__device__ float d_srp[BB*7*NT];
__device__ float d_scp[BB*7*NT];
__device__ float d_sr[BB*NT];
__device__ float d_sc[BB*NT];
__device__ float d_du0[BB*NR];
__device__ float d_du1[BB*NR];
__device__ float d_du2[BB*NR];
__device__ float d_du3[BB*NR];
__device__ float d_hpart[144];

// ---------------- FMA-only helpers ----------------
__device__ __forceinline__ float fexp(float x) {
    x = fmaxf(x, -87.0f);
    const float L2E_HI = 1.4426950216293335f;
    const float L2E_LO = 1.9259630e-8f;
    float y = fmaf(x, L2E_HI, 12582912.0f);
    int   n = __float_as_int(y) - 0x4B400000;
    float fi = y - 12582912.0f;
    float r = fmaf(x, L2E_HI, -fi);
    r = fmaf(x, L2E_LO, r);
    float t = r * 0.69314718055994531f;
    float p = 1.3888889e-3f;
    p = fmaf(p, t, 8.3333333e-3f);
    p = fmaf(p, t, 4.1666667e-2f);
    p = fmaf(p, t, 1.6666667e-1f);
    p = fmaf(p, t, 0.5f);
    p = fmaf(p, t, 1.0f);
    p = fmaf(p, t, 1.0f);
    return p * __int_as_float((n + 127) << 23);
}

__device__ __forceinline__ float frcp(float x) {
    float r = __int_as_float(0x7EF311C3 - __float_as_int(x));
    r = r * fmaf(-x, r, 2.0f);
    r = r * fmaf(-x, r, 2.0f);
    r = r * fmaf(-x, r, 2.0f);
    return r;
}

__device__ __forceinline__ void cp16(void* s, const void* g) {
    unsigned int sa = (unsigned int)__cvta_generic_to_shared(s);
    asm volatile("cp.async.cg.shared.global [%0], [%1], 16;" :: "r"(sa), "l"(g));
}

__device__ __forceinline__ float4 tf32x4(float4 v) {
    v.x = wmma::__float_to_tf32(v.x);
    v.y = wmma::__float_to_tf32(v.y);
    v.z = wmma::__float_to_tf32(v.z);
    v.w = wmma::__float_to_tf32(v.w);
    return v;
}

// ---------------- packed f32x2 helpers (FFMA2 path, sm_103a) ----------------
__device__ __forceinline__ unsigned long long pk2(float lo, float hi) {
    unsigned long long r;
    asm("mov.b64 %0, {%1, %2};" : "=l"(r) : "f"(lo), "f"(hi));
    return r;
}
__device__ __forceinline__ void upk2(unsigned long long v, float& lo, float& hi) {
    asm("mov.b64 {%0, %1}, %2;" : "=f"(lo), "=f"(hi) : "l"(v));
}
__device__ __forceinline__ unsigned long long fma2(unsigned long long a,
                                                   unsigned long long b,
                                                   unsigned long long c) {
    unsigned long long d;
    asm("fma.rn.f32x2 %0, %1, %2, %3;" : "=l"(d) : "l"(a), "l"(b), "l"(c));
    return d;
}
__device__ __forceinline__ unsigned long long add2(unsigned long long a,
                                                   unsigned long long b) {
    unsigned long long d;
    asm("add.rn.f32x2 %0, %1, %2;" : "=l"(d) : "l"(a), "l"(b));
    return d;
}
__device__ __forceinline__ unsigned long long mul2(unsigned long long a,
                                                   unsigned long long b) {
    unsigned long long d;
    asm("mul.rn.f32x2 %0, %1, %2;" : "=l"(d) : "l"(a), "l"(b));
    return d;
}

// ---------------- 1) normalize + tf32-round; also emit rounded raw x3/x4 ----------------
__global__ void __launch_bounds__(256) k_normalize(
    const float* __restrict__ x1, const float* __restrict__ x2,
    const float* __restrict__ x3, const float* __restrict__ x4)
{
    int gw   = blockIdx.x * 8 + (threadIdx.x >> 5);
    int lane = threadIdx.x & 31;
    int which = (gw >= BB*NT) ? 1 : 0;
    int r     = which ? gw - BB*NT : gw;
    int b = r / NT, i = r % NT;
    const float* src;
    float* rawdst = nullptr;
    if (i < NR) {
        src = (which ? x2 : x1) + ((size_t)(b*NR + i)) * DD;
    } else {
        size_t off = ((size_t)(b*NP + (i - NR))) * DD;
        src = (which ? x4 : x3) + off;
        rawdst = (which ? d_x4r : d_x3r) + off;
    }
    float* dst = (which ? d_f2n : d_f1n) + (size_t)r * DD;

    float4 v0 = *(const float4*)(src + lane*4);
    float4 v1 = *(const float4*)(src + 128 + lane*4);
    if (rawdst) {
        *(float4*)(rawdst + lane*4)       = tf32x4(v0);
        *(float4*)(rawdst + 128 + lane*4) = tf32x4(v1);
    }
    float sq = v0.x*v0.x + v0.y*v0.y + v0.z*v0.z + v0.w*v0.w
             + v1.x*v1.x + v1.y*v1.y + v1.z*v1.z + v1.w*v1.w;
    #pragma unroll
    for (int o = 16; o; o >>= 1) sq += __shfl_xor_sync(0xffffffffu, sq, o);
    float rn = 1.0f / fmaxf(sqrtf(sq), 1e-12f);
    v0.x *= rn; v0.y *= rn; v0.z *= rn; v0.w *= rn;
    v1.x *= rn; v1.y *= rn; v1.z *= rn; v1.w *= rn;
    *(float4*)(dst + lane*4)       = tf32x4(v0);
    *(float4*)(dst + 128 + lane*4) = tf32x4(v1);
}

// ---------------- 2) pipelined tf32 GEMM + exp + partial sums (R7-proven) ----------------
#define LDA 36                // ≡4 mod 32 -> conflict-free fragment loads
#define LDE 132
#define STAGE (128*LDA)       // 4608 floats
#define SIM_SMEM (4*STAGE*4)  // 73728 bytes

__global__ void __launch_bounds__(256) k_simgemm()
{
    extern __shared__ float sh[];
    __shared__ float colacc[128];

    int b  = blockIdx.z;
    int m0 = blockIdx.y * 128, n0 = blockIdx.x * 128;
    if (m0 >= NR && n0 >= NR) return;   // padding x padding feeds nothing

    const float* Ag = d_f1n + (size_t)b * NT * DD + (size_t)m0 * DD;
    const float* Bg = d_f2n + (size_t)b * NT * DD + (size_t)n0 * DD;

    int tid = threadIdx.x;
    int wid = tid >> 5;
    int warp_m = wid >> 2;
    int warp_n = wid & 3;

    wmma::fragment<wmma::accumulator,16,16,8,float> acc[4][2];
    #pragma unroll
    for (int mt = 0; mt < 4; mt++)
        #pragma unroll
        for (int nt = 0; nt < 2; nt++)
            wmma::fill_fragment(acc[mt][nt], 0.0f);

    int lrow = tid >> 3;
    int lc4  = (tid & 7) * 4;

    {
        float* A = sh; float* B = sh + STAGE;
        #pragma unroll
        for (int u = 0; u < 4; u++) {
            int row = lrow + 32*u;
            cp16(&A[row*LDA + lc4], Ag + (size_t)row*DD + lc4);
            cp16(&B[row*LDA + lc4], Bg + (size_t)row*DD + lc4);
        }
        asm volatile("cp.async.commit_group;");
    }

    for (int kc = 0; kc < 8; kc++) {
        if (kc < 7) {
            float* A = sh + ((kc+1)&1)*2*STAGE;
            float* B = A + STAGE;
            int k0 = (kc+1)*32;
            #pragma unroll
            for (int u = 0; u < 4; u++) {
                int row = lrow + 32*u;
                cp16(&A[row*LDA + lc4], Ag + (size_t)row*DD + k0 + lc4);
                cp16(&B[row*LDA + lc4], Bg + (size_t)row*DD + k0 + lc4);
            }
            asm volatile("cp.async.commit_group;");
            asm volatile("cp.async.wait_group 1;");
        } else {
            asm volatile("cp.async.wait_group 0;");
        }
        __syncthreads();
        const float* A = sh + (kc&1)*2*STAGE;
        const float* B = A + STAGE;
        #pragma unroll
        for (int ks = 0; ks < 4; ks++) {
            wmma::fragment<wmma::matrix_b,16,16,8,wmma::precision::tf32,wmma::col_major> bf[2];
            #pragma unroll
            for (int nt = 0; nt < 2; nt++)
                wmma::load_matrix_sync(bf[nt], &B[(warp_n*32 + nt*16)*LDA + ks*8], LDA);
            #pragma unroll
            for (int mt = 0; mt < 4; mt++) {
                wmma::fragment<wmma::matrix_a,16,16,8,wmma::precision::tf32,wmma::row_major> af;
                wmma::load_matrix_sync(af, &A[(warp_m*64 + mt*16)*LDA + ks*8], LDA);
                #pragma unroll
                for (int nt = 0; nt < 2; nt++)
                    wmma::mma_sync(acc[mt][nt], af, bf[nt], acc[mt][nt]);
            }
        }
        __syncthreads();
    }

    if (tid < 128) colacc[tid] = 0.f;
    __syncthreads();

    bool inblk = (m0 < NR) && (n0 < NR);
    int r   = tid >> 2;
    int seg = tid & 3;

    #pragma unroll
    for (int phase = 0; phase < 2; phase++) {
        if (warp_m == phase) {
            #pragma unroll
            for (int mt = 0; mt < 4; mt++)
                #pragma unroll
                for (int nt = 0; nt < 2; nt++)
                    wmma::store_matrix_sync(&sh[(mt*16)*LDE + warp_n*32 + nt*16],
                                            acc[mt][nt], LDE, wmma::mem_row_major);
        }
        __syncthreads();

        int ig = m0 + phase*64 + r;
        float rsum = 0.f;
        float* Srow = d_S + ((size_t)b*NR + ig)*NR + n0 + seg*32;
        #pragma unroll
        for (int q = 0; q < 8; q++) {
            float4 v4 = *(float4*)&sh[r*LDE + seg*32 + q*4];
            v4.x = fexp(10.0f * v4.x);
            v4.y = fexp(10.0f * v4.y);
            v4.z = fexp(10.0f * v4.z);
            v4.w = fexp(10.0f * v4.w);
            rsum += (v4.x + v4.y) + (v4.z + v4.w);
            *(float4*)&sh[r*LDE + seg*32 + q*4] = v4;
            if (inblk) *(float4*)(Srow + q*4) = v4;
        }
        rsum += __shfl_down_sync(0xffffffffu, rsum, 2);
        rsum += __shfl_down_sync(0xffffffffu, rsum, 1);
        if (seg == 0) d_srp[((size_t)b*7 + (n0 >> 7))*NT + ig] = rsum;
        __syncthreads();

        int col  = tid >> 1;
        int half = tid & 1;
        float cs = 0.f;
        #pragma unroll
        for (int rr = 0; rr < 32; rr++)
            cs += sh[(half*32 + rr)*LDE + col];
        cs += __shfl_down_sync(0xffffffffu, cs, 1);
        if (half == 0) colacc[col] += cs;
        __syncthreads();
    }
    if (tid < 128) d_scp[((size_t)b*7 + (m0 >> 7))*NT + n0 + tid] = colacc[tid];
}

// ---------------- 3) reduce partial sums (real rows/cols only) ----------------
__global__ void k_sums()
{
    int idx = blockIdx.x * 256 + threadIdx.x;   // 2*BB*NR
    if (idx >= 2*BB*NR) return;
    int which = idx >= BB*NR;
    int r = which ? idx - BB*NR : idx;
    int b = r >> 9, i = r & 511;
    const float* P = (which ? d_scp : d_srp) + (size_t)b*7*NT + i;
    float s = 0.f;
    #pragma unroll
    for (int t = 0; t < 7; t++) s += P[(size_t)t*NT];
    (which ? d_sc : d_sr)[b*NT + i] = s;
}

// ---------------- 4) cost: C = 1 - s/(sc+sr-s) in-place + C^T ----------------
__global__ void k_cost()
{
    int b  = blockIdx.z;
    int j0 = blockIdx.x * 32, i0 = blockIdx.y * 32;
    float* S  = d_S  + (size_t)b * NR * NR;
    float* CT = d_CT + (size_t)b * NR * NR;
    __shared__ float tile[32][33];
    int tx = threadIdx.x, ty = threadIdx.y;   // (32, 8)
    int j = j0 + tx;
    float scv = d_sc[b * NT + j];
    #pragma unroll
    for (int r = 0; r < 4; r++) {
        int i = i0 + ty + 8*r;
        float s   = S[(size_t)i * NR + j];
        float den = scv + d_sr[b * NT + i] - s;
        float c   = fmaf(-s, frcp(den), 1.0f);
        S[(size_t)i * NR + j] = c;
        tile[ty + 8*r][tx] = c;
    }
    __syncthreads();
    #pragma unroll
    for (int r = 0; r < 4; r++) {
        int ii = j0 + ty + 8*r;
        int jj = i0 + tx;
        CT[(size_t)ii * NR + jj] = tile[tx][ty + 8*r];
    }
}

// ---------------- 5) softmin: warp per row, packed-f32x2 exp ----------------
__global__ void __launch_bounds__(256) k_softmin_pair(
    const float* __restrict__ hf, const float* __restrict__ hg,
    const float* __restrict__ oldf, const float* __restrict__ oldg,
    float* __restrict__ outf, float* __restrict__ outg,
    float eps, float inv_eps, int avg)
{
    int gw   = blockIdx.x * 8 + (threadIdx.x >> 5);
    int lane = threadIdx.x & 31;
    int side = (gw >= BB*NR) ? 1 : 0;
    int row  = side ? gw - BB*NR : gw;
    int b    = row >> 9;
    const float* Crow = (side ? d_CT : d_S) + (size_t)row * NR;
    const float* hv   = side ? hg : hf;
    const float* oldv = side ? oldg : oldf;
    float*       ov   = side ? outg : outf;
    const float* hb   = hv ? hv + (b << 9) : nullptr;

    float a[16];
    #pragma unroll
    for (int q = 0; q < 4; q++) {
        int j = q*128 + lane*4;
        float4 c4 = *(const float4*)(Crow + j);
        if (hb) {
            float4 h4 = *(const float4*)(hb + j);
            a[q*4+0] = (h4.x - c4.x) * inv_eps;
            a[q*4+1] = (h4.y - c4.y) * inv_eps;
            a[q*4+2] = (h4.z - c4.z) * inv_eps;
            a[q*4+3] = (h4.w - c4.w) * inv_eps;
        } else {
            a[q*4+0] = -c4.x * inv_eps;
            a[q*4+1] = -c4.y * inv_eps;
            a[q*4+2] = -c4.z * inv_eps;
            a[q*4+3] = -c4.w * inv_eps;
        }
    }
    float m = a[0];
    #pragma unroll
    for (int u = 1; u < 16; u++) m = fmaxf(m, a[u]);
    #pragma unroll
    for (int o = 16; o; o >>= 1) m = fmaxf(m, __shfl_xor_sync(0xffffffffu, m, o));

    // packed exp: ACC += 2^n0..1 * poly(r0..1), all f32x2 FFMA
    const unsigned long long L2E2   = pk2(1.4426950216293335f, 1.4426950216293335f);
    const unsigned long long MAGIC2 = pk2(12582912.0f, 12582912.0f);
    const unsigned long long NMAG2  = pk2(-12582912.0f, -12582912.0f);
    const unsigned long long LN2_2  = pk2(0.69314718055994531f, 0.69314718055994531f);
    const unsigned long long K6 = pk2(1.3888889e-3f, 1.3888889e-3f);
    const unsigned long long K5 = pk2(8.3333333e-3f, 8.3333333e-3f);
    const unsigned long long K4 = pk2(4.1666667e-2f, 4.1666667e-2f);
    const unsigned long long K3 = pk2(1.6666667e-1f, 1.6666667e-1f);
    const unsigned long long K2 = pk2(0.5f, 0.5f);
    const unsigned long long K1 = pk2(1.0f, 1.0f);

    unsigned long long ACC = 0ULL;   // (0.0f, 0.0f)
    #pragma unroll
    for (int u = 0; u < 8; u++) {
        float x0 = fmaxf(a[2*u]   - m, -87.0f);
        float x1 = fmaxf(a[2*u+1] - m, -87.0f);
        unsigned long long X = pk2(x0, x1);
        unsigned long long Y = fma2(X, L2E2, MAGIC2);
        unsigned int ylo = (unsigned int)Y;
        unsigned int yhi = (unsigned int)(Y >> 32);
        unsigned int s0 = (ylo + (127u - 0x4B400000u)) << 23;
        unsigned int s1 = (yhi + (127u - 0x4B400000u)) << 23;
        unsigned long long FI = add2(Y, NMAG2);
        unsigned long long R  = fma2(X, L2E2, FI ^ 0x8000000080000000ULL);
        unsigned long long T  = mul2(R, LN2_2);
        unsigned long long P  = fma2(K6, T, K5);
        P = fma2(P, T, K4);
        P = fma2(P, T, K3);
        P = fma2(P, T, K2);
        P = fma2(P, T, K1);
        P = fma2(P, T, K1);
        unsigned long long S = ((unsigned long long)s1 << 32) | (unsigned long long)s0;
        ACC = fma2(P, S, ACC);       // exp value = P*S, accumulated packed
    }
    float e0, e1;
    upk2(ACC, e0, e1);
    float s = e0 + e1;
    #pragma unroll
    for (int o = 16; o; o >>= 1) s += __shfl_xor_sync(0xffffffffu, s, o);
    if (lane == 0) {
        float val = -eps * (m + logf(s));
        if (avg) val = 0.5f * (oldv[row] + val);
        ov[row] = val;
    }
}

// ---------------- 6) hinge GEMM (pipelined tf32, pre-rounded inputs) ----------------
__global__ void __launch_bounds__(256) k_hinge()
{
    extern __shared__ float sh[];
    int b  = blockIdx.z;
    int m0 = blockIdx.y * 128, n0 = blockIdx.x * 128;
    const float* Ag = d_x3r + (size_t)b * NP * DD + (size_t)m0 * DD;
    const float* Bg = d_x4r + (size_t)b * NP * DD + (size_t)n0 * DD;

    int tid = threadIdx.x;
    int wid = tid >> 5;
    int warp_m = wid >> 2;
    int warp_n = wid & 3;

    wmma::fragment<wmma::accumulator,16,16,8,float> acc[4][2];
    #pragma unroll
    for (int mt = 0; mt < 4; mt++)
        #pragma unroll
        for (int nt = 0; nt < 2; nt++)
            wmma::fill_fragment(acc[mt][nt], 0.0f);

    int lrow = tid >> 3;
    int lc4  = (tid & 7) * 4;

    {
        float* A = sh; float* B = sh + STAGE;
        #pragma unroll
        for (int u = 0; u < 4; u++) {
            int row = lrow + 32*u;
            cp16(&A[row*LDA + lc4], Ag + (size_t)row*DD + lc4);
            cp16(&B[row*LDA + lc4], Bg + (size_t)row*DD + lc4);
        }
        asm volatile("cp.async.commit_group;");
    }

    for (int kc = 0; kc < 8; kc++) {
        if (kc < 7) {
            float* A = sh + ((kc+1)&1)*2*STAGE;
            float* B = A + STAGE;
            int k0 = (kc+1)*32;
            #pragma unroll
            for (int u = 0; u < 4; u++) {
                int row = lrow + 32*u;
                cp16(&A[row*LDA + lc4], Ag + (size_t)row*DD + k0 + lc4);
                cp16(&B[row*LDA + lc4], Bg + (size_t)row*DD + k0 + lc4);
            }
            asm volatile("cp.async.commit_group;");
            asm volatile("cp.async.wait_group 1;");
        } else {
            asm volatile("cp.async.wait_group 0;");
        }
        __syncthreads();
        const float* A = sh + (kc&1)*2*STAGE;
        const float* B = A + STAGE;
        #pragma unroll
        for (int ks = 0; ks < 4; ks++) {
            wmma::fragment<wmma::matrix_b,16,16,8,wmma::precision::tf32,wmma::col_major> bf[2];
            #pragma unroll
            for (int nt = 0; nt < 2; nt++)
                wmma::load_matrix_sync(bf[nt], &B[(warp_n*32 + nt*16)*LDA + ks*8], LDA);
            #pragma unroll
            for (int mt = 0; mt < 4; mt++) {
                wmma::fragment<wmma::matrix_a,16,16,8,wmma::precision::tf32,wmma::row_major> af;
                wmma::load_matrix_sync(af, &A[(warp_m*64 + mt*16)*LDA + ks*8], LDA);
                #pragma unroll
                for (int nt = 0; nt < 2; nt++)
                    wmma::mma_sync(acc[mt][nt], af, bf[nt], acc[mt][nt]);
            }
        }
        __syncthreads();
    }

    float loc = 0.f;
    #pragma unroll
    for (int mt = 0; mt < 4; mt++)
        #pragma unroll
        for (int nt = 0; nt < 2; nt++)
            #pragma unroll
            for (int e = 0; e < acc[mt][nt].num_elements; e++)
                loc += fmaxf(0.1f - acc[mt][nt].x[e], 0.0f);

    __shared__ float red[8];
    #pragma unroll
    for (int o = 16; o; o >>= 1) loc += __shfl_xor_sync(0xffffffffu, loc, o);
    if ((tid & 31) == 0) red[tid >> 5] = loc;
    __syncthreads();
    if (tid == 0) {
        float tot = 0.f;
        #pragma unroll
        for (int w = 0; w < 8; w++) tot += red[w];
        d_hpart[blockIdx.z * 9 + blockIdx.y * 3 + blockIdx.x] = tot;
    }
}

// ---------------- 7) deterministic final reduction ----------------
__global__ void k_finalize(float* __restrict__ out)
{
    int t = threadIdx.x;
    double acc = 0.0;
    for (int idx = t; idx < BB*NR; idx += 256)
        acc += (double)d_du2[idx] + (double)d_du3[idx];
    double h = 0.0;
    for (int idx = t; idx < 144; idx += 256) h += (double)d_hpart[idx];
    __shared__ double sa[256];
    __shared__ double sb[256];
    sa[t] = acc; sb[t] = h;
    __syncthreads();
    for (int o = 128; o; o >>= 1) {
        if (t < o) { sa[t] += sa[t + o]; sb[t] += sb[t + o]; }
        __syncthreads();
    }
    if (t == 0) {
        out[0] = (float)sb[0];
        out[1] = (float)(sa[0] / (double)BB);
    }
}

// ---------------- host ----------------
extern "C" void kernel_launch(void* const* d_in, const int* in_sizes, int n_in,
                              void* d_out, int out_size)
{
    const float* x1 = (const float*)d_in[0];
    const float* x2 = (const float*)d_in[1];
    const float* x3 = (const float*)d_in[2];
    const float* x4 = (const float*)d_in[3];
    float* out = (float*)d_out;

    cudaFuncSetAttribute(k_simgemm, cudaFuncAttributeMaxDynamicSharedMemorySize, SIM_SMEM);
    cudaFuncSetAttribute(k_hinge,   cudaFuncAttributeMaxDynamicSharedMemorySize, SIM_SMEM);

    float *p0, *p1, *p2, *p3;
    cudaGetSymbolAddress((void**)&p0, d_du0);
    cudaGetSymbolAddress((void**)&p1, d_du1);
    cudaGetSymbolAddress((void**)&p2, d_du2);
    cudaGetSymbolAddress((void**)&p3, d_du3);

    k_normalize<<<2*BB*NT/8, 256>>>(x1, x2, x3, x4);
    k_simgemm<<<dim3(7, 7, BB), 256, SIM_SMEM>>>();
    k_sums<<<(2*BB*NR + 255)/256, 256>>>();
    k_cost<<<dim3(NR/32, NR/32, BB), dim3(32, 8)>>>();
    k_hinge<<<dim3(3, 3, BB), 256, SIM_SMEM>>>();

    const float EPS[8] = {9.0f, 9.0f, 2.25f, 0.5625f, 0.140625f,
                          0.03515625f, 0.0087890625f, 0.0025f};

    k_softmin_pair<<<2*BB*NR/8, 256>>>(nullptr, nullptr, nullptr, nullptr,
                                       p0, p1, 9.0f, 1.0f/9.0f, 0);

    float *fc = p0, *gc = p1, *fa = p2, *ga = p3;
    for (int k = 0; k < 8; k++) {
        float e = EPS[k], ie = 1.0f / e;
        k_softmin_pair<<<2*BB*NR/8, 256>>>(gc, fc, fc, gc, fa, ga, e, ie, 1);
        float* tf = fc; fc = fa; fa = tf;
        float* tg = gc; gc = ga; ga = tg;
    }
    k_softmin_pair<<<2*BB*NR/8, 256>>>(gc, fc, nullptr, nullptr, p2, p3,
                                       0.0025f, 400.0f, 0);

    k_finalize<<<1, 256>>>(out);
}

// round 10
// speedup vs baseline: 1.4724x; 1.4724x over previous
#include <cuda_runtime.h>
#include <cstdint>
#include <mma.h>
#include <math.h>

using namespace nvcuda;

#define BB 16      // batch
#define NR 512     // real points
#define NP 384     // padding points
#define NT 896     // total points per side
#define DD 256     // feature dim

// ---------------- scratch ----------------
__device__ float d_f1n[BB*NT*DD];       // normalized f1 (tf32-rounded)
__device__ float d_f2n[BB*NT*DD];       // normalized f2 (tf32-rounded)
__device__ float d_x3r[BB*NP*DD];       // tf32-rounded raw x3
__device__ float d_x4r[BB*NP*DD];       // tf32-rounded raw x4
__device__ float d_S  [BB*NR*NR];       // S then C (in-place)
__device__ float d_CT [BB*NR*NR];       // C transposed
__device__ float d_srp[BB*7*NT];
__device__ float d_scp[BB*7*NT];
__device__ float d_sr[BB*NT];
__device__ float d_sc[BB*NT];
__device__ float d_du0[BB*NR];
__device__ float d_du1[BB*NR];
__device__ float d_du2[BB*NR];
__device__ float d_du3[BB*NR];
__device__ float d_hpart[144];

// ---------------- FMA-only helpers ----------------
// 2^y for y <= ~15, clamped below at -125.  Degree-6 poly in r = y - round(y).
__device__ __forceinline__ float fexp2s(float y, float& scale) {
    y = fmaxf(y, -125.0f);
    float Y = y + 12582912.0f;           // round-to-nearest-int magic
    int   n = __float_as_int(Y);         // 0x4B400000 + round(y)
    float fi = Y - 12582912.0f;
    float r = y - fi;                    // r in [-0.5, 0.5]
    float p =           1.5403530e-4f;   // (ln2)^6/720
    p = fmaf(p, r, 1.3333558e-3f);
    p = fmaf(p, r, 9.6181291e-3f);
    p = fmaf(p, r, 5.5504109e-2f);
    p = fmaf(p, r, 2.4022651e-1f);
    p = fmaf(p, r, 6.9314718e-1f);
    p = fmaf(p, r, 1.0f);
    scale = __int_as_float((unsigned)((n - 0x4B400000 + 127) << 23));
    return p;
}

__device__ __forceinline__ float fexp2v(float y) {
    float s;
    float p = fexp2s(y, s);
    return p * s;
}

__device__ __forceinline__ float frcp(float x) {
    float r = __int_as_float(0x7EF311C3 - __float_as_int(x));
    r = r * fmaf(-x, r, 2.0f);
    r = r * fmaf(-x, r, 2.0f);
    r = r * fmaf(-x, r, 2.0f);
    return r;
}

__device__ __forceinline__ void cp16(void* s, const void* g) {
    unsigned int sa = (unsigned int)__cvta_generic_to_shared(s);
    asm volatile("cp.async.cg.shared.global [%0], [%1], 16;" :: "r"(sa), "l"(g));
}

__device__ __forceinline__ float4 tf32x4(float4 v) {
    v.x = wmma::__float_to_tf32(v.x);
    v.y = wmma::__float_to_tf32(v.y);
    v.z = wmma::__float_to_tf32(v.z);
    v.w = wmma::__float_to_tf32(v.w);
    return v;
}

// ---------------- 1) normalize + tf32-round; also emit rounded raw x3/x4 ----------------
__global__ void __launch_bounds__(256) k_normalize(
    const float* __restrict__ x1, const float* __restrict__ x2,
    const float* __restrict__ x3, const float* __restrict__ x4)
{
    int gw   = blockIdx.x * 8 + (threadIdx.x >> 5);
    int lane = threadIdx.x & 31;
    int which = (gw >= BB*NT) ? 1 : 0;
    int r     = which ? gw - BB*NT : gw;
    int b = r / NT, i = r % NT;
    const float* src;
    float* rawdst = nullptr;
    if (i < NR) {
        src = (which ? x2 : x1) + ((size_t)(b*NR + i)) * DD;
    } else {
        size_t off = ((size_t)(b*NP + (i - NR))) * DD;
        src = (which ? x4 : x3) + off;
        rawdst = (which ? d_x4r : d_x3r) + off;
    }
    float* dst = (which ? d_f2n : d_f1n) + (size_t)r * DD;

    float4 v0 = *(const float4*)(src + lane*4);
    float4 v1 = *(const float4*)(src + 128 + lane*4);
    if (rawdst) {
        *(float4*)(rawdst + lane*4)       = tf32x4(v0);
        *(float4*)(rawdst + 128 + lane*4) = tf32x4(v1);
    }
    float sq = v0.x*v0.x + v0.y*v0.y + v0.z*v0.z + v0.w*v0.w
             + v1.x*v1.x + v1.y*v1.y + v1.z*v1.z + v1.w*v1.w;
    #pragma unroll
    for (int o = 16; o; o >>= 1) sq += __shfl_xor_sync(0xffffffffu, sq, o);
    float rn = 1.0f / fmaxf(sqrtf(sq), 1e-12f);
    v0.x *= rn; v0.y *= rn; v0.z *= rn; v0.w *= rn;
    v1.x *= rn; v1.y *= rn; v1.z *= rn; v1.w *= rn;
    *(float4*)(dst + lane*4)       = tf32x4(v0);
    *(float4*)(dst + 128 + lane*4) = tf32x4(v1);
}

// ---------------- 2) pipelined tf32 GEMM + exp + partial sums (R7-proven) ----------------
#define LDA 36                // ≡4 mod 32 -> conflict-free fragment loads
#define LDE 132
#define STAGE (128*LDA)       // 4608 floats
#define SIM_SMEM (4*STAGE*4)  // 73728 bytes
#define L2E10 14.4269504088896340736f   // 10 * log2(e)

__global__ void __launch_bounds__(256) k_simgemm()
{
    extern __shared__ float sh[];
    __shared__ float colacc[128];

    int b  = blockIdx.z;
    int m0 = blockIdx.y * 128, n0 = blockIdx.x * 128;
    if (m0 >= NR && n0 >= NR) return;   // padding x padding feeds nothing

    const float* Ag = d_f1n + (size_t)b * NT * DD + (size_t)m0 * DD;
    const float* Bg = d_f2n + (size_t)b * NT * DD + (size_t)n0 * DD;

    int tid = threadIdx.x;
    int wid = tid >> 5;
    int warp_m = wid >> 2;
    int warp_n = wid & 3;

    wmma::fragment<wmma::accumulator,16,16,8,float> acc[4][2];
    #pragma unroll
    for (int mt = 0; mt < 4; mt++)
        #pragma unroll
        for (int nt = 0; nt < 2; nt++)
            wmma::fill_fragment(acc[mt][nt], 0.0f);

    int lrow = tid >> 3;
    int lc4  = (tid & 7) * 4;

    {
        float* A = sh; float* B = sh + STAGE;
        #pragma unroll
        for (int u = 0; u < 4; u++) {
            int row = lrow + 32*u;
            cp16(&A[row*LDA + lc4], Ag + (size_t)row*DD + lc4);
            cp16(&B[row*LDA + lc4], Bg + (size_t)row*DD + lc4);
        }
        asm volatile("cp.async.commit_group;");
    }

    for (int kc = 0; kc < 8; kc++) {
        if (kc < 7) {
            float* A = sh + ((kc+1)&1)*2*STAGE;
            float* B = A + STAGE;
            int k0 = (kc+1)*32;
            #pragma unroll
            for (int u = 0; u < 4; u++) {
                int row = lrow + 32*u;
                cp16(&A[row*LDA + lc4], Ag + (size_t)row*DD + k0 + lc4);
                cp16(&B[row*LDA + lc4], Bg + (size_t)row*DD + k0 + lc4);
            }
            asm volatile("cp.async.commit_group;");
            asm volatile("cp.async.wait_group 1;");
        } else {
            asm volatile("cp.async.wait_group 0;");
        }
        __syncthreads();
        const float* A = sh + (kc&1)*2*STAGE;
        const float* B = A + STAGE;
        #pragma unroll
        for (int ks = 0; ks < 4; ks++) {
            wmma::fragment<wmma::matrix_b,16,16,8,wmma::precision::tf32,wmma::col_major> bf[2];
            #pragma unroll
            for (int nt = 0; nt < 2; nt++)
                wmma::load_matrix_sync(bf[nt], &B[(warp_n*32 + nt*16)*LDA + ks*8], LDA);
            #pragma unroll
            for (int mt = 0; mt < 4; mt++) {
                wmma::fragment<wmma::matrix_a,16,16,8,wmma::precision::tf32,wmma::row_major> af;
                wmma::load_matrix_sync(af, &A[(warp_m*64 + mt*16)*LDA + ks*8], LDA);
                #pragma unroll
                for (int nt = 0; nt < 2; nt++)
                    wmma::mma_sync(acc[mt][nt], af, bf[nt], acc[mt][nt]);
            }
        }
        __syncthreads();
    }

    if (tid < 128) colacc[tid] = 0.f;
    __syncthreads();

    bool inblk = (m0 < NR) && (n0 < NR);
    int r   = tid >> 2;
    int seg = tid & 3;

    #pragma unroll
    for (int phase = 0; phase < 2; phase++) {
        if (warp_m == phase) {
            #pragma unroll
            for (int mt = 0; mt < 4; mt++)
                #pragma unroll
                for (int nt = 0; nt < 2; nt++)
                    wmma::store_matrix_sync(&sh[(mt*16)*LDE + warp_n*32 + nt*16],
                                            acc[mt][nt], LDE, wmma::mem_row_major);
        }
        __syncthreads();

        int ig = m0 + phase*64 + r;
        float rsum = 0.f;
        float* Srow = d_S + ((size_t)b*NR + ig)*NR + n0 + seg*32;
        #pragma unroll
        for (int q = 0; q < 8; q++) {
            float4 v4 = *(float4*)&sh[r*LDE + seg*32 + q*4];
            v4.x = fexp2v(L2E10 * v4.x);
            v4.y = fexp2v(L2E10 * v4.y);
            v4.z = fexp2v(L2E10 * v4.z);
            v4.w = fexp2v(L2E10 * v4.w);
            rsum += (v4.x + v4.y) + (v4.z + v4.w);
            *(float4*)&sh[r*LDE + seg*32 + q*4] = v4;
            if (inblk) *(float4*)(Srow + q*4) = v4;
        }
        rsum += __shfl_down_sync(0xffffffffu, rsum, 2);
        rsum += __shfl_down_sync(0xffffffffu, rsum, 1);
        if (seg == 0) d_srp[((size_t)b*7 + (n0 >> 7))*NT + ig] = rsum;
        __syncthreads();

        int col  = tid >> 1;
        int half = tid & 1;
        float cs = 0.f;
        #pragma unroll
        for (int rr = 0; rr < 32; rr++)
            cs += sh[(half*32 + rr)*LDE + col];
        cs += __shfl_down_sync(0xffffffffu, cs, 1);
        if (half == 0) colacc[col] += cs;
        __syncthreads();
    }
    if (tid < 128) d_scp[((size_t)b*7 + (m0 >> 7))*NT + n0 + tid] = colacc[tid];
}

// ---------------- 3) reduce partial sums (real rows/cols only) ----------------
__global__ void k_sums()
{
    int idx = blockIdx.x * 256 + threadIdx.x;   // 2*BB*NR
    if (idx >= 2*BB*NR) return;
    int which = idx >= BB*NR;
    int r = which ? idx - BB*NR : idx;
    int b = r >> 9, i = r & 511;
    const float* P = (which ? d_scp : d_srp) + (size_t)b*7*NT + i;
    float s = 0.f;
    #pragma unroll
    for (int t = 0; t < 7; t++) s += P[(size_t)t*NT];
    (which ? d_sc : d_sr)[b*NT + i] = s;
}

// ---------------- 4) cost: C = 1 - s/(sc+sr-s) in-place + C^T ----------------
__global__ void k_cost()
{
    int b  = blockIdx.z;
    int j0 = blockIdx.x * 32, i0 = blockIdx.y * 32;
    float* S  = d_S  + (size_t)b * NR * NR;
    float* CT = d_CT + (size_t)b * NR * NR;
    __shared__ float tile[32][33];
    int tx = threadIdx.x, ty = threadIdx.y;   // (32, 8)
    int j = j0 + tx;
    float scv = d_sc[b * NT + j];
    #pragma unroll
    for (int r = 0; r < 4; r++) {
        int i = i0 + ty + 8*r;
        float s   = S[(size_t)i * NR + j];
        float den = scv + d_sr[b * NT + i] - s;
        float c   = fmaf(-s, frcp(den), 1.0f);
        S[(size_t)i * NR + j] = c;
        tile[ty + 8*r][tx] = c;
    }
    __syncthreads();
    #pragma unroll
    for (int r = 0; r < 4; r++) {
        int ii = j0 + ty + 8*r;
        int jj = i0 + tx;
        CT[(size_t)ii * NR + jj] = tile[tx][ty + 8*r];
    }
}

// ---------------- 5) softmin: warp per row, exp2-domain, 1024-block single wave ----------------
// keps = log2(e)/eps;  val = -eps*(m2*ln2 + log(sum 2^(a - m2)))
__global__ void __launch_bounds__(256) k_softmin_pair(
    const float* __restrict__ hf, const float* __restrict__ hg,
    const float* __restrict__ oldf, const float* __restrict__ oldg,
    float* __restrict__ outf, float* __restrict__ outg,
    float eps, float keps, int avg)
{
    int lane   = threadIdx.x & 31;
    int warp0  = blockIdx.x * 8 + (threadIdx.x >> 5);
    int stride = gridDim.x * 8;

    for (int gw = warp0; gw < 2*BB*NR; gw += stride) {
        int side = (gw >= BB*NR) ? 1 : 0;
        int row  = side ? gw - BB*NR : gw;
        int b    = row >> 9;
        const float* Crow = (side ? d_CT : d_S) + (size_t)row * NR;
        const float* hv   = side ? hg : hf;
        const float* oldv = side ? oldg : oldf;
        float*       ov   = side ? outg : outf;
        const float* hb   = hv ? hv + (b << 9) : nullptr;

        float a[16];
        #pragma unroll
        for (int q = 0; q < 4; q++) {
            int j = q*128 + lane*4;
            float4 c4 = *(const float4*)(Crow + j);
            if (hb) {
                float4 h4 = *(const float4*)(hb + j);
                a[q*4+0] = (h4.x - c4.x) * keps;
                a[q*4+1] = (h4.y - c4.y) * keps;
                a[q*4+2] = (h4.z - c4.z) * keps;
                a[q*4+3] = (h4.w - c4.w) * keps;
            } else {
                a[q*4+0] = -c4.x * keps;
                a[q*4+1] = -c4.y * keps;
                a[q*4+2] = -c4.z * keps;
                a[q*4+3] = -c4.w * keps;
            }
        }
        float m = a[0];
        #pragma unroll
        for (int u = 1; u < 16; u++) m = fmaxf(m, a[u]);
        #pragma unroll
        for (int o = 16; o; o >>= 1) m = fmaxf(m, __shfl_xor_sync(0xffffffffu, m, o));

        float s0 = 0.f, s1 = 0.f;       // two chains for ILP, fixed order
        #pragma unroll
        for (int u = 0; u < 8; u++) {
            float sc0, sc1;
            float p0 = fexp2s(a[2*u]   - m, sc0);
            float p1 = fexp2s(a[2*u+1] - m, sc1);
            s0 = fmaf(p0, sc0, s0);
            s1 = fmaf(p1, sc1, s1);
        }
        float s = s0 + s1;
        #pragma unroll
        for (int o = 16; o; o >>= 1) s += __shfl_xor_sync(0xffffffffu, s, o);
        if (lane == 0) {
            float val = -eps * (fmaf(m, 0.69314718055994531f, logf(s)));
            if (avg) val = 0.5f * (oldv[row] + val);
            ov[row] = val;
        }
    }
}

// ---------------- 6) hinge GEMM (pipelined tf32, pre-rounded inputs) ----------------
__global__ void __launch_bounds__(256) k_hinge()
{
    extern __shared__ float sh[];
    int b  = blockIdx.z;
    int m0 = blockIdx.y * 128, n0 = blockIdx.x * 128;
    const float* Ag = d_x3r + (size_t)b * NP * DD + (size_t)m0 * DD;
    const float* Bg = d_x4r + (size_t)b * NP * DD + (size_t)n0 * DD;

    int tid = threadIdx.x;
    int wid = tid >> 5;
    int warp_m = wid >> 2;
    int warp_n = wid & 3;

    wmma::fragment<wmma::accumulator,16,16,8,float> acc[4][2];
    #pragma unroll
    for (int mt = 0; mt < 4; mt++)
        #pragma unroll
        for (int nt = 0; nt < 2; nt++)
            wmma::fill_fragment(acc[mt][nt], 0.0f);

    int lrow = tid >> 3;
    int lc4  = (tid & 7) * 4;

    {
        float* A = sh; float* B = sh + STAGE;
        #pragma unroll
        for (int u = 0; u < 4; u++) {
            int row = lrow + 32*u;
            cp16(&A[row*LDA + lc4], Ag + (size_t)row*DD + lc4);
            cp16(&B[row*LDA + lc4], Bg + (size_t)row*DD + lc4);
        }
        asm volatile("cp.async.commit_group;");
    }

    for (int kc = 0; kc < 8; kc++) {
        if (kc < 7) {
            float* A = sh + ((kc+1)&1)*2*STAGE;
            float* B = A + STAGE;
            int k0 = (kc+1)*32;
            #pragma unroll
            for (int u = 0; u < 4; u++) {
                int row = lrow + 32*u;
                cp16(&A[row*LDA + lc4], Ag + (size_t)row*DD + k0 + lc4);
                cp16(&B[row*LDA + lc4], Bg + (size_t)row*DD + k0 + lc4);
            }
            asm volatile("cp.async.commit_group;");
            asm volatile("cp.async.wait_group 1;");
        } else {
            asm volatile("cp.async.wait_group 0;");
        }
        __syncthreads();
        const float* A = sh + (kc&1)*2*STAGE;
        const float* B = A + STAGE;
        #pragma unroll
        for (int ks = 0; ks < 4; ks++) {
            wmma::fragment<wmma::matrix_b,16,16,8,wmma::precision::tf32,wmma::col_major> bf[2];
            #pragma unroll
            for (int nt = 0; nt < 2; nt++)
                wmma::load_matrix_sync(bf[nt], &B[(warp_n*32 + nt*16)*LDA + ks*8], LDA);
            #pragma unroll
            for (int mt = 0; mt < 4; mt++) {
                wmma::fragment<wmma::matrix_a,16,16,8,wmma::precision::tf32,wmma::row_major> af;
                wmma::load_matrix_sync(af, &A[(warp_m*64 + mt*16)*LDA + ks*8], LDA);
                #pragma unroll
                for (int nt = 0; nt < 2; nt++)
                    wmma::mma_sync(acc[mt][nt], af, bf[nt], acc[mt][nt]);
            }
        }
        __syncthreads();
    }

    float loc = 0.f;
    #pragma unroll
    for (int mt = 0; mt < 4; mt++)
        #pragma unroll
        for (int nt = 0; nt < 2; nt++)
            #pragma unroll
            for (int e = 0; e < acc[mt][nt].num_elements; e++)
                loc += fmaxf(0.1f - acc[mt][nt].x[e], 0.0f);

    __shared__ float red[8];
    #pragma unroll
    for (int o = 16; o; o >>= 1) loc += __shfl_xor_sync(0xffffffffu, loc, o);
    if ((tid & 31) == 0) red[tid >> 5] = loc;
    __syncthreads();
    if (tid == 0) {
        float tot = 0.f;
        #pragma unroll
        for (int w = 0; w < 8; w++) tot += red[w];
        d_hpart[blockIdx.z * 9 + blockIdx.y * 3 + blockIdx.x] = tot;
    }
}

// ---------------- 7) deterministic final reduction ----------------
__global__ void k_finalize(float* __restrict__ out)
{
    int t = threadIdx.x;
    double acc = 0.0;
    for (int idx = t; idx < BB*NR; idx += 256)
        acc += (double)d_du2[idx] + (double)d_du3[idx];
    double h = 0.0;
    for (int idx = t; idx < 144; idx += 256) h += (double)d_hpart[idx];
    __shared__ double sa[256];
    __shared__ double sb[256];
    sa[t] = acc; sb[t] = h;
    __syncthreads();
    for (int o = 128; o; o >>= 1) {
        if (t < o) { sa[t] += sa[t + o]; sb[t] += sb[t + o]; }
        __syncthreads();
    }
    if (t == 0) {
        out[0] = (float)sb[0];
        out[1] = (float)(sa[0] / (double)BB);
    }
}

// ---------------- host ----------------
extern "C" void kernel_launch(void* const* d_in, const int* in_sizes, int n_in,
                              void* d_out, int out_size)
{
    const float* x1 = (const float*)d_in[0];
    const float* x2 = (const float*)d_in[1];
    const float* x3 = (const float*)d_in[2];
    const float* x4 = (const float*)d_in[3];
    float* out = (float*)d_out;

    cudaFuncSetAttribute(k_simgemm, cudaFuncAttributeMaxDynamicSharedMemorySize, SIM_SMEM);
    cudaFuncSetAttribute(k_hinge,   cudaFuncAttributeMaxDynamicSharedMemorySize, SIM_SMEM);

    float *p0, *p1, *p2, *p3;
    cudaGetSymbolAddress((void**)&p0, d_du0);
    cudaGetSymbolAddress((void**)&p1, d_du1);
    cudaGetSymbolAddress((void**)&p2, d_du2);
    cudaGetSymbolAddress((void**)&p3, d_du3);

    k_normalize<<<2*BB*NT/8, 256>>>(x1, x2, x3, x4);
    k_simgemm<<<dim3(7, 7, BB), 256, SIM_SMEM>>>();
    k_sums<<<(2*BB*NR + 255)/256, 256>>>();
    k_cost<<<dim3(NR/32, NR/32, BB), dim3(32, 8)>>>();
    k_hinge<<<dim3(3, 3, BB), 256, SIM_SMEM>>>();

    const float EPS[8] = {9.0f, 9.0f, 2.25f, 0.5625f, 0.140625f,
                          0.03515625f, 0.0087890625f, 0.0025f};
    const float L2E = 1.4426950408889634f;

    // 1024 blocks: 8192 warps, exactly 2 rows per warp, one fully-resident wave
    k_softmin_pair<<<1024, 256>>>(nullptr, nullptr, nullptr, nullptr,
                                  p0, p1, 9.0f, L2E/9.0f, 0);

    float *fc = p0, *gc = p1, *fa = p2, *ga = p3;
    for (int k = 0; k < 8; k++) {
        float e = EPS[k];
        k_softmin_pair<<<1024, 256>>>(gc, fc, fc, gc, fa, ga, e, L2E/e, 1);
        float* tf = fc; fc = fa; fa = tf;
        float* tg = gc; gc = ga; ga = tg;
    }
    k_softmin_pair<<<1024, 256>>>(gc, fc, nullptr, nullptr, p2, p3,
                                  0.0025f, L2E/0.0025f, 0);

    k_finalize<<<1, 256>>>(out);
}

// round 12
// speedup vs baseline: 1.5631x; 1.0616x over previous
#include <cuda_runtime.h>
#include <cstdint>
#include <mma.h>
#include <math.h>

using namespace nvcuda;

#define BB 16      // batch
#define NR 512     // real points
#define NP 384     // padding points
#define NT 896     // total points per side
#define DD 256     // feature dim

// ---------------- scratch ----------------
__device__ float d_f1n[BB*NT*DD];       // normalized f1 (tf32-rounded)
__device__ float d_f2n[BB*NT*DD];       // normalized f2 (tf32-rounded)
__device__ float d_x3r[BB*NP*DD];       // tf32-rounded raw x3
__device__ float d_x4r[BB*NP*DD];       // tf32-rounded raw x4
__device__ float d_S  [BB*NR*NR];       // S then C (in-place)
__device__ float d_CT [BB*NR*NR];       // C transposed
__device__ float d_srp[BB*7*NT];
__device__ float d_scp[BB*7*NT];
__device__ float d_du0[BB*NR];
__device__ float d_du1[BB*NR];
__device__ float d_du2[BB*NR];
__device__ float d_du3[BB*NR];
__device__ float d_hpart[144];

// ---------------- FMA-only helpers ----------------
// 2^y for y <= ~15, clamped below at -125.  Degree-6 poly in r = y - round(y).
__device__ __forceinline__ float fexp2s(float y, float& scale) {
    y = fmaxf(y, -125.0f);
    float Y = y + 12582912.0f;           // round-to-nearest-int magic
    int   n = __float_as_int(Y);         // 0x4B400000 + round(y)
    float fi = Y - 12582912.0f;
    float r = y - fi;                    // r in [-0.5, 0.5]
    float p =           1.5403530e-4f;   // (ln2)^6/720
    p = fmaf(p, r, 1.3333558e-3f);
    p = fmaf(p, r, 9.6181291e-3f);
    p = fmaf(p, r, 5.5504109e-2f);
    p = fmaf(p, r, 2.4022651e-1f);
    p = fmaf(p, r, 6.9314718e-1f);
    p = fmaf(p, r, 1.0f);
    scale = __int_as_float((unsigned)((n - 0x4B400000 + 127) << 23));
    return p;
}

__device__ __forceinline__ float fexp2v(float y) {
    float s;
    float p = fexp2s(y, s);
    return p * s;
}

__device__ __forceinline__ float frcp(float x) {
    float r = __int_as_float(0x7EF311C3 - __float_as_int(x));
    r = r * fmaf(-x, r, 2.0f);
    r = r * fmaf(-x, r, 2.0f);
    r = r * fmaf(-x, r, 2.0f);
    return r;
}

__device__ __forceinline__ void cp16(void* s, const void* g) {
    unsigned int sa = (unsigned int)__cvta_generic_to_shared(s);
    asm volatile("cp.async.cg.shared.global [%0], [%1], 16;" :: "r"(sa), "l"(g));
}

__device__ __forceinline__ float4 tf32x4(float4 v) {
    v.x = wmma::__float_to_tf32(v.x);
    v.y = wmma::__float_to_tf32(v.y);
    v.z = wmma::__float_to_tf32(v.z);
    v.w = wmma::__float_to_tf32(v.w);
    return v;
}

// ---------------- 1) normalize + tf32-round; also emit rounded raw x3/x4 ----------------
__global__ void __launch_bounds__(256) k_normalize(
    const float* __restrict__ x1, const float* __restrict__ x2,
    const float* __restrict__ x3, const float* __restrict__ x4)
{
    int gw   = blockIdx.x * 8 + (threadIdx.x >> 5);
    int lane = threadIdx.x & 31;
    int which = (gw >= BB*NT) ? 1 : 0;
    int r     = which ? gw - BB*NT : gw;
    int b = r / NT, i = r % NT;
    const float* src;
    float* rawdst = nullptr;
    if (i < NR) {
        src = (which ? x2 : x1) + ((size_t)(b*NR + i)) * DD;
    } else {
        size_t off = ((size_t)(b*NP + (i - NR))) * DD;
        src = (which ? x4 : x3) + off;
        rawdst = (which ? d_x4r : d_x3r) + off;
    }
    float* dst = (which ? d_f2n : d_f1n) + (size_t)r * DD;

    float4 v0 = *(const float4*)(src + lane*4);
    float4 v1 = *(const float4*)(src + 128 + lane*4);
    if (rawdst) {
        *(float4*)(rawdst + lane*4)       = tf32x4(v0);
        *(float4*)(rawdst + 128 + lane*4) = tf32x4(v1);
    }
    float sq = v0.x*v0.x + v0.y*v0.y + v0.z*v0.z + v0.w*v0.w
             + v1.x*v1.x + v1.y*v1.y + v1.z*v1.z + v1.w*v1.w;
    #pragma unroll
    for (int o = 16; o; o >>= 1) sq += __shfl_xor_sync(0xffffffffu, sq, o);
    float rn = 1.0f / fmaxf(sqrtf(sq), 1e-12f);
    v0.x *= rn; v0.y *= rn; v0.z *= rn; v0.w *= rn;
    v1.x *= rn; v1.y *= rn; v1.z *= rn; v1.w *= rn;
    *(float4*)(dst + lane*4)       = tf32x4(v0);
    *(float4*)(dst + 128 + lane*4) = tf32x4(v1);
}

// ---------------- 2) pipelined tf32 GEMM, 4 warps x (64x64 tiles) ----------------
#define LDA 36                // ≡4 mod 32 -> conflict-free fragment loads
#define LDE 132
#define STAGE (128*LDA)       // 4608 floats
#define SIM_SMEM (4*STAGE*4)  // 73728 bytes (>= 128*LDE*4 = 67584 for epilogue)
#define L2E10 14.4269504088896340736f   // 10 * log2(e)

__global__ void __launch_bounds__(128) k_simgemm()
{
    extern __shared__ float sh[];

    int b  = blockIdx.z;
    int m0 = blockIdx.y * 128, n0 = blockIdx.x * 128;
    if (m0 >= NR && n0 >= NR) return;   // padding x padding feeds nothing

    const float* Ag = d_f1n + (size_t)b * NT * DD + (size_t)m0 * DD;
    const float* Bg = d_f2n + (size_t)b * NT * DD + (size_t)n0 * DD;

    int tid = threadIdx.x;              // 128 threads, 4 warps
    int wid = tid >> 5;
    int warp_m = wid >> 1;              // 0..1
    int warp_n = wid & 1;               // 0..1

    wmma::fragment<wmma::accumulator,16,16,8,float> acc[4][4];
    #pragma unroll
    for (int mt = 0; mt < 4; mt++)
        #pragma unroll
        for (int nt = 0; nt < 4; nt++)
            wmma::fill_fragment(acc[mt][nt], 0.0f);

    int lrow = tid >> 3;                // 0..15
    int lc4  = (tid & 7) * 4;

    {
        float* A = sh; float* B = sh + STAGE;
        #pragma unroll
        for (int u = 0; u < 8; u++) {
            int row = lrow + 16*u;
            cp16(&A[row*LDA + lc4], Ag + (size_t)row*DD + lc4);
            cp16(&B[row*LDA + lc4], Bg + (size_t)row*DD + lc4);
        }
        asm volatile("cp.async.commit_group;");
    }

    for (int kc = 0; kc < 8; kc++) {
        if (kc < 7) {
            float* A = sh + ((kc+1)&1)*2*STAGE;
            float* B = A + STAGE;
            int k0 = (kc+1)*32;
            #pragma unroll
            for (int u = 0; u < 8; u++) {
                int row = lrow + 16*u;
                cp16(&A[row*LDA + lc4], Ag + (size_t)row*DD + k0 + lc4);
                cp16(&B[row*LDA + lc4], Bg + (size_t)row*DD + k0 + lc4);
            }
            asm volatile("cp.async.commit_group;");
            asm volatile("cp.async.wait_group 1;");
        } else {
            asm volatile("cp.async.wait_group 0;");
        }
        __syncthreads();
        const float* A = sh + (kc&1)*2*STAGE;
        const float* B = A + STAGE;
        #pragma unroll
        for (int ks = 0; ks < 4; ks++) {
            wmma::fragment<wmma::matrix_a,16,16,8,wmma::precision::tf32,wmma::row_major> af[4];
            wmma::fragment<wmma::matrix_b,16,16,8,wmma::precision::tf32,wmma::col_major> bf[4];
            #pragma unroll
            for (int mt = 0; mt < 4; mt++)
                wmma::load_matrix_sync(af[mt], &A[(warp_m*64 + mt*16)*LDA + ks*8], LDA);
            #pragma unroll
            for (int nt = 0; nt < 4; nt++)
                wmma::load_matrix_sync(bf[nt], &B[(warp_n*64 + nt*16)*LDA + ks*8], LDA);
            #pragma unroll
            for (int mt = 0; mt < 4; mt++)
                #pragma unroll
                for (int nt = 0; nt < 4; nt++)
                    wmma::mma_sync(acc[mt][nt], af[mt], bf[nt], acc[mt][nt]);
        }
        __syncthreads();
    }

    // epilogue: store all acc to sh[128][LDE], then thread-per-row exp + sums
    #pragma unroll
    for (int mt = 0; mt < 4; mt++)
        #pragma unroll
        for (int nt = 0; nt < 4; nt++)
            wmma::store_matrix_sync(&sh[(warp_m*64 + mt*16)*LDE + warp_n*64 + nt*16],
                                    acc[mt][nt], LDE, wmma::mem_row_major);
    __syncthreads();

    bool inblk = (m0 < NR) && (n0 < NR);
    int ig = m0 + tid;
    float rsum = 0.f;
    float* Srow = d_S + ((size_t)b*NR + ig)*NR + n0;
    #pragma unroll
    for (int q = 0; q < 32; q++) {
        float4 v4 = *(float4*)&sh[tid*LDE + q*4];
        v4.x = fexp2v(L2E10 * v4.x);
        v4.y = fexp2v(L2E10 * v4.y);
        v4.z = fexp2v(L2E10 * v4.z);
        v4.w = fexp2v(L2E10 * v4.w);
        rsum += (v4.x + v4.y) + (v4.z + v4.w);
        *(float4*)&sh[tid*LDE + q*4] = v4;
        if (inblk) *(float4*)(Srow + q*4) = v4;
    }
    d_srp[((size_t)b*7 + (n0 >> 7))*NT + ig] = rsum;
    __syncthreads();

    float cs = 0.f;
    #pragma unroll 8
    for (int r = 0; r < 128; r++) cs += sh[r*LDE + tid];
    d_scp[((size_t)b*7 + (m0 >> 7))*NT + n0 + tid] = cs;
}

// ---------------- 3) cost (with fused partial-sum reduction): C = 1 - s/(sc+sr-s) + C^T ----------------
__global__ void k_cost()
{
    int b  = blockIdx.z;
    int j0 = blockIdx.x * 32, i0 = blockIdx.y * 32;
    float* S  = d_S  + (size_t)b * NR * NR;
    float* CT = d_CT + (size_t)b * NR * NR;
    __shared__ float tile[32][33];
    __shared__ float srv[32];
    __shared__ float scv[32];
    int tx = threadIdx.x, ty = threadIdx.y;   // (32, 8)
    int tid = ty*32 + tx;

    // fused k_sums: 64 threads reduce the 7 partials for this block's rows/cols
    if (tid < 64) {
        int which = tid >> 5;    // 0: col sums, 1: row sums
        int idx   = tid & 31;
        const float* P = which ? (d_srp + (size_t)b*7*NT + i0 + idx)
                               : (d_scp + (size_t)b*7*NT + j0 + idx);
        float s = 0.f;
        #pragma unroll
        for (int t = 0; t < 7; t++) s += P[(size_t)t*NT];
        (which ? srv : scv)[idx] = s;
    }
    __syncthreads();

    int j = j0 + tx;
    float sc_j = scv[tx];
    #pragma unroll
    for (int r = 0; r < 4; r++) {
        int i = i0 + ty + 8*r;
        float s   = S[(size_t)i * NR + j];
        float den = sc_j + srv[ty + 8*r] - s;
        float c   = fmaf(-s, frcp(den), 1.0f);
        S[(size_t)i * NR + j] = c;
        tile[ty + 8*r][tx] = c;
    }
    __syncthreads();
    #pragma unroll
    for (int r = 0; r < 4; r++) {
        int ii = j0 + ty + 8*r;
        int jj = i0 + tx;
        CT[(size_t)ii * NR + jj] = tile[tx][ty + 8*r];
    }
}

// ---------------- 4) softmin: warp per row, exp2-domain, 1024-block single wave ----------------
__global__ void __launch_bounds__(256) k_softmin_pair(
    const float* __restrict__ hf, const float* __restrict__ hg,
    const float* __restrict__ oldf, const float* __restrict__ oldg,
    float* __restrict__ outf, float* __restrict__ outg,
    float eps, float keps, int avg)
{
    int lane   = threadIdx.x & 31;
    int warp0  = blockIdx.x * 8 + (threadIdx.x >> 5);
    int stride = gridDim.x * 8;

    for (int gw = warp0; gw < 2*BB*NR; gw += stride) {
        int side = (gw >= BB*NR) ? 1 : 0;
        int row  = side ? gw - BB*NR : gw;
        int b    = row >> 9;
        const float* Crow = (side ? d_CT : d_S) + (size_t)row * NR;
        const float* hv   = side ? hg : hf;
        const float* oldv = side ? oldg : oldf;
        float*       ov   = side ? outg : outf;
        const float* hb   = hv ? hv + (b << 9) : nullptr;

        float a[16];
        #pragma unroll
        for (int q = 0; q < 4; q++) {
            int j = q*128 + lane*4;
            float4 c4 = *(const float4*)(Crow + j);
            if (hb) {
                float4 h4 = *(const float4*)(hb + j);
                a[q*4+0] = (h4.x - c4.x) * keps;
                a[q*4+1] = (h4.y - c4.y) * keps;
                a[q*4+2] = (h4.z - c4.z) * keps;
                a[q*4+3] = (h4.w - c4.w) * keps;
            } else {
                a[q*4+0] = -c4.x * keps;
                a[q*4+1] = -c4.y * keps;
                a[q*4+2] = -c4.z * keps;
                a[q*4+3] = -c4.w * keps;
            }
        }
        float m = a[0];
        #pragma unroll
        for (int u = 1; u < 16; u++) m = fmaxf(m, a[u]);
        #pragma unroll
        for (int o = 16; o; o >>= 1) m = fmaxf(m, __shfl_xor_sync(0xffffffffu, m, o));

        float s0 = 0.f, s1 = 0.f;
        #pragma unroll
        for (int u = 0; u < 8; u++) {
            float sc0, sc1;
            float p0 = fexp2s(a[2*u]   - m, sc0);
            float p1 = fexp2s(a[2*u+1] - m, sc1);
            s0 = fmaf(p0, sc0, s0);
            s1 = fmaf(p1, sc1, s1);
        }
        float s = s0 + s1;
        #pragma unroll
        for (int o = 16; o; o >>= 1) s += __shfl_xor_sync(0xffffffffu, s, o);
        if (lane == 0) {
            float val = -eps * (fmaf(m, 0.69314718055994531f, logf(s)));
            if (avg) val = 0.5f * (oldv[row] + val);
            ov[row] = val;
        }
    }
}

// ---------------- 5) hinge GEMM (pipelined tf32, pre-rounded inputs) ----------------
__global__ void __launch_bounds__(256) k_hinge()
{
    extern __shared__ float sh[];
    int b  = blockIdx.z;
    int m0 = blockIdx.y * 128, n0 = blockIdx.x * 128;
    const float* Ag = d_x3r + (size_t)b * NP * DD + (size_t)m0 * DD;
    const float* Bg = d_x4r + (size_t)b * NP * DD + (size_t)n0 * DD;

    int tid = threadIdx.x;
    int wid = tid >> 5;
    int warp_m = wid >> 2;
    int warp_n = wid & 3;

    wmma::fragment<wmma::accumulator,16,16,8,float> acc[4][2];
    #pragma unroll
    for (int mt = 0; mt < 4; mt++)
        #pragma unroll
        for (int nt = 0; nt < 2; nt++)
            wmma::fill_fragment(acc[mt][nt], 0.0f);

    int lrow = tid >> 3;
    int lc4  = (tid & 7) * 4;

    {
        float* A = sh; float* B = sh + STAGE;
        #pragma unroll
        for (int u = 0; u < 4; u++) {
            int row = lrow + 32*u;
            cp16(&A[row*LDA + lc4], Ag + (size_t)row*DD + lc4);
            cp16(&B[row*LDA + lc4], Bg + (size_t)row*DD + lc4);
        }
        asm volatile("cp.async.commit_group;");
    }

    for (int kc = 0; kc < 8; kc++) {
        if (kc < 7) {
            float* A = sh + ((kc+1)&1)*2*STAGE;
            float* B = A + STAGE;
            int k0 = (kc+1)*32;
            #pragma unroll
            for (int u = 0; u < 4; u++) {
                int row = lrow + 32*u;
                cp16(&A[row*LDA + lc4], Ag + (size_t)row*DD + k0 + lc4);
                cp16(&B[row*LDA + lc4], Bg + (size_t)row*DD + k0 + lc4);
            }
            asm volatile("cp.async.commit_group;");
            asm volatile("cp.async.wait_group 1;");
        } else {
            asm volatile("cp.async.wait_group 0;");
        }
        __syncthreads();
        const float* A = sh + (kc&1)*2*STAGE;
        const float* B = A + STAGE;
        #pragma unroll
        for (int ks = 0; ks < 4; ks++) {
            wmma::fragment<wmma::matrix_b,16,16,8,wmma::precision::tf32,wmma::col_major> bf[2];
            #pragma unroll
            for (int nt = 0; nt < 2; nt++)
                wmma::load_matrix_sync(bf[nt], &B[(warp_n*32 + nt*16)*LDA + ks*8], LDA);
            #pragma unroll
            for (int mt = 0; mt < 4; mt++) {
                wmma::fragment<wmma::matrix_a,16,16,8,wmma::precision::tf32,wmma::row_major> af;
                wmma::load_matrix_sync(af, &A[(warp_m*64 + mt*16)*LDA + ks*8], LDA);
                #pragma unroll
                for (int nt = 0; nt < 2; nt++)
                    wmma::mma_sync(acc[mt][nt], af, bf[nt], acc[mt][nt]);
            }
        }
        __syncthreads();
    }

    float loc = 0.f;
    #pragma unroll
    for (int mt = 0; mt < 4; mt++)
        #pragma unroll
        for (int nt = 0; nt < 2; nt++)
            #pragma unroll
            for (int e = 0; e < acc[mt][nt].num_elements; e++)
                loc += fmaxf(0.1f - acc[mt][nt].x[e], 0.0f);

    __shared__ float red[8];
    #pragma unroll
    for (int o = 16; o; o >>= 1) loc += __shfl_xor_sync(0xffffffffu, loc, o);
    if ((tid & 31) == 0) red[tid >> 5] = loc;
    __syncthreads();
    if (tid == 0) {
        float tot = 0.f;
        #pragma unroll
        for (int w = 0; w < 8; w++) tot += red[w];
        d_hpart[blockIdx.z * 9 + blockIdx.y * 3 + blockIdx.x] = tot;
    }
}

// ---------------- 6) deterministic final reduction ----------------
__global__ void k_finalize(float* __restrict__ out)
{
    int t = threadIdx.x;
    double acc = 0.0;
    for (int idx = t; idx < BB*NR; idx += 256)
        acc += (double)d_du2[idx] + (double)d_du3[idx];
    double h = 0.0;
    for (int idx = t; idx < 144; idx += 256) h += (double)d_hpart[idx];
    __shared__ double sa[256];
    __shared__ double sb[256];
    sa[t] = acc; sb[t] = h;
    __syncthreads();
    for (int o = 128; o; o >>= 1) {
        if (t < o) { sa[t] += sa[t + o]; sb[t] += sb[t + o]; }
        __syncthreads();
    }
    if (t == 0) {
        out[0] = (float)sb[0];
        out[1] = (float)(sa[0] / (double)BB);
    }
}

// ---------------- host ----------------
extern "C" void kernel_launch(void* const* d_in, const int* in_sizes, int n_in,
                              void* d_out, int out_size)
{
    const float* x1 = (const float*)d_in[0];
    const float* x2 = (const float*)d_in[1];
    const float* x3 = (const float*)d_in[2];
    const float* x4 = (const float*)d_in[3];
    float* out = (float*)d_out;

    cudaFuncSetAttribute(k_simgemm, cudaFuncAttributeMaxDynamicSharedMemorySize, SIM_SMEM);
    cudaFuncSetAttribute(k_hinge,   cudaFuncAttributeMaxDynamicSharedMemorySize, SIM_SMEM);

    float *p0, *p1, *p2, *p3;
    cudaGetSymbolAddress((void**)&p0, d_du0);
    cudaGetSymbolAddress((void**)&p1, d_du1);
    cudaGetSymbolAddress((void**)&p2, d_du2);
    cudaGetSymbolAddress((void**)&p3, d_du3);

    k_normalize<<<2*BB*NT/8, 256>>>(x1, x2, x3, x4);
    k_simgemm<<<dim3(7, 7, BB), 128, SIM_SMEM>>>();
    k_cost<<<dim3(NR/32, NR/32, BB), dim3(32, 8)>>>();
    k_hinge<<<dim3(3, 3, BB), 256, SIM_SMEM>>>();

    const float EPS[8] = {9.0f, 9.0f, 2.25f, 0.5625f, 0.140625f,
                          0.03515625f, 0.0087890625f, 0.0025f};
    const float L2E = 1.4426950408889634f;

    // 1024 blocks: 8192 warps, exactly 2 rows per warp, one fully-resident wave
    k_softmin_pair<<<1024, 256>>>(nullptr, nullptr, nullptr, nullptr,
                                  p0, p1, 9.0f, L2E/9.0f, 0);

    float *fc = p0, *gc = p1, *fa = p2, *ga = p3;
    for (int k = 0; k < 8; k++) {
        float e = EPS[k];
        k_softmin_pair<<<1024, 256>>>(gc, fc, fc, gc, fa, ga, e, L2E/e, 1);
        float* tf = fc; fc = fa; fa = tf;
        float* tg = gc; gc = ga; ga = tg;
    }
    k_softmin_pair<<<1024, 256>>>(gc, fc, nullptr, nullptr, p2, p3,
                                  0.0025f, L2E/0.0025f, 0);

    k_finalize<<<1, 256>>>(out);
}